// round 16
// baseline (speedup 1.0000x reference)
#include <cuda_runtime.h>
#include <cuda_bf16.h>

// Problem constants (fixed by dataset):
//   walk:  int32 [B=1024, L=80]
//   neg:   int32 [B=1024, A=76, NEG=4]
//   embed: f32   [1000000, D=128]
//   out:   f32 scalar = (sum softplus(-pos) + sum softplus(neg)) / (B*A*8)
#define L_WALK   80
#define W_WIN    5
#define A_ANC    (L_WALK - W_WIN + 1)     // 76
#define NNEG     4
#define DIM      128
#define NVEC     (DIM / 4)                // 32 float4 per row
#define NTHREADS 512
#define NWARPS   (NTHREADS / 32)          // 16

#define ROWS_PER L_WALK                   // all 80 walk rows staged
#define STAGE_V  (ROWS_PER * NVEC)        // 2560 float4 copies = 5 per thread

static __global__ void zero_kernel(float* out) {
    if (threadIdx.x == 0) out[0] = 0.0f;
}

__device__ __forceinline__ float warp_reduce_sum(float v) {
    v += __shfl_xor_sync(0xffffffffu, v, 16);
    v += __shfl_xor_sync(0xffffffffu, v, 8);
    v += __shfl_xor_sync(0xffffffffu, v, 4);
    v += __shfl_xor_sync(0xffffffffu, v, 2);
    v += __shfl_xor_sync(0xffffffffu, v, 1);
    return v;
}

// Pairwise combining reduce: lanes with (lane & off)==0 end up holding the
// a-reduction, lanes with the bit set hold the b-reduction.
__device__ __forceinline__ float cmb(float a, float b, int off, int lane) {
    float send = (lane & off) ? a : b;
    float keep = (lane & off) ? b : a;
    return keep + __shfl_xor_sync(0xffffffffu, send, off);
}

// softplus(x) = max(x,0) + log(1 + exp(-|x|)); fast-math variants are
// accurate to ~1e-7 absolute here, far inside the 1e-3 rel-err budget.
__device__ __forceinline__ float softplus_f(float x) {
    return fmaxf(x, 0.0f) + __logf(1.0f + __expf(-fabsf(x)));
}

__device__ __forceinline__ float dot4(float4 a, float4 b) {
    return a.x * b.x + a.y * b.y + a.z * b.z + a.w * b.w;
}

__global__ __launch_bounds__(NTHREADS, 4)
void sgns_kernel(const int* __restrict__ walk,
                 const int* __restrict__ neg,
                 const float* __restrict__ embed,
                 float* __restrict__ out,
                 float inv_total) {
    __shared__ float4 srow[ROWS_PER][NVEC];   // 80 x 512B = 40 KB
    __shared__ int    swalk[ROWS_PER];
    __shared__ int    sneg[A_ANC * NNEG];     // 304 ints
    __shared__ float  wsum[NWARPS];

    const int wb   = blockIdx.x;              // one block per walk
    const int tid  = threadIdx.x;
    const int lane = tid & 31;
    const int wid  = tid >> 5;

    if (tid < ROWS_PER)
        swalk[tid] = walk[(size_t)wb * L_WALK + tid];
    if (tid < A_ANC * NNEG)
        sneg[tid] = neg[(size_t)wb * A_ANC * NNEG + tid];
    __syncthreads();

    // Stage all 80 walk-row embeddings (2560 float4s = exactly 5 per thread,
    // no bounds checks) with batched independent LDGs (MLP=3 then MLP=2).
    {
        const int f0 = tid, f1 = tid + NTHREADS, f2 = tid + 2 * NTHREADS;
        const float4 t0 = __ldg((const float4*)(embed + (size_t)swalk[f0 >> 5] * DIM) + (f0 & 31));
        const float4 t1 = __ldg((const float4*)(embed + (size_t)swalk[f1 >> 5] * DIM) + (f1 & 31));
        const float4 t2 = __ldg((const float4*)(embed + (size_t)swalk[f2 >> 5] * DIM) + (f2 & 31));
        srow[f0 >> 5][f0 & 31] = t0;
        srow[f1 >> 5][f1 & 31] = t1;
        srow[f2 >> 5][f2 & 31] = t2;
    }
    {
        const int f3 = tid + 3 * NTHREADS, f4 = tid + 4 * NTHREADS;
        const float4 t3 = __ldg((const float4*)(embed + (size_t)swalk[f3 >> 5] * DIM) + (f3 & 31));
        const float4 t4 = __ldg((const float4*)(embed + (size_t)swalk[f4 >> 5] * DIM) + (f4 & 31));
        srow[f3 >> 5][f3 & 31] = t3;
        srow[f4 >> 5][f4 & 31] = t4;
    }
    __syncthreads();

    float acc = 0.0f;   // per-lane partial (8 softplus lanes contribute)

    // One warp per anchor; 16 warps stride over the 76 anchors.
    for (int a = wid; a < A_ANC; a += NWARPS) {
        // Issue the 4 random gathers first so DRAM latency overlaps pos work.
        const int i0 = sneg[a * NNEG + 0];
        const int i1 = sneg[a * NNEG + 1];
        const int i2 = sneg[a * NNEG + 2];
        const int i3 = sneg[a * NNEG + 3];
        const float4 v0 = __ldg((const float4*)(embed + (size_t)i0 * DIM) + lane);
        const float4 v1 = __ldg((const float4*)(embed + (size_t)i1 * DIM) + lane);
        const float4 v2 = __ldg((const float4*)(embed + (size_t)i2 * DIM) + lane);
        const float4 v3 = __ldg((const float4*)(embed + (size_t)i3 * DIM) + lane);

        const float4 va = srow[a][lane];

        // Positive contexts (smem, reused 5x per row).
        const float p0 = dot4(va, srow[a + 1][lane]);
        const float p1 = dot4(va, srow[a + 2][lane]);
        const float p2 = dot4(va, srow[a + 3][lane]);
        const float p3 = dot4(va, srow[a + 4][lane]);

        // Negative dots (consume the in-flight gathers).
        const float p4 = dot4(va, v0);
        const float p5 = dot4(va, v1);
        const float p6 = dot4(va, v2);
        const float p7 = dot4(va, v3);

        // Multi-value warp reduction: 9 shfls reduce all 8 dots.
        //   bit16 -> pos vs neg, bits {8,4} -> which of the 4 within group.
        float r10 = cmb(p0, p4, 16, lane);
        float r11 = cmb(p1, p5, 16, lane);
        float r12 = cmb(p2, p6, 16, lane);
        float r13 = cmb(p3, p7, 16, lane);
        float q0  = cmb(r10, r11, 8, lane);
        float q1  = cmb(r12, r13, 8, lane);
        float r   = cmb(q0, q1, 4, lane);
        r += __shfl_xor_sync(0xffffffffu, r, 2);
        r += __shfl_xor_sync(0xffffffffu, r, 1);

        // Lanes 0,4,8,...,28 each hold one of the 8 full dot products.
        // bit16 set => negative-sample logit (softplus(+x)), else softplus(-x).
        if ((lane & 3) == 0) {
            const float x = (lane & 16) ? r : -r;
            acc += softplus_f(x);
        }
    }

    acc = warp_reduce_sum(acc);
    if (lane == 0) wsum[wid] = acc;
    __syncthreads();

    if (tid == 0) {
        float s = 0.0f;
        #pragma unroll
        for (int i = 0; i < NWARPS; i++) s += wsum[i];
        atomicAdd(out, s * inv_total);
    }
}

extern "C" void kernel_launch(void* const* d_in, const int* in_sizes, int n_in,
                              void* d_out, int out_size) {
    const int*   walk  = (const int*)d_in[0];
    const int*   neg   = (const int*)d_in[1];
    const float* embed = (const float*)d_in[2];
    float*       out   = (float*)d_out;

    const int B = in_sizes[0] / L_WALK;                 // 1024
    const float inv_total = 1.0f / ((float)B * A_ANC * (W_WIN - 1 + NNEG));

    zero_kernel<<<1, 32>>>(out);
    sgns_kernel<<<B, NTHREADS>>>(walk, neg, embed, out, inv_total);
}

// round 17
// speedup vs baseline: 1.0563x; 1.0563x over previous
#include <cuda_runtime.h>
#include <cuda_bf16.h>

// Problem constants (fixed by dataset):
//   walk:  int32 [B=1024, L=80]
//   neg:   int32 [B=1024, A=76, NEG=4]
//   embed: f32   [1000000, D=128]
//   out:   f32 scalar = (sum softplus(-pos) + sum softplus(neg)) / (B*A*8)
#define L_WALK   80
#define W_WIN    5
#define A_ANC    (L_WALK - W_WIN + 1)     // 76
#define NNEG     4
#define DIM      128
#define NVEC     (DIM / 4)                // 32 float4 per row
#define NTHREADS 256
#define NWARPS   (NTHREADS / 32)

#define SPLIT    2
#define ANC_PER  (A_ANC / SPLIT)          // 38 anchors per block
#define ROWS_PER (ANC_PER + W_WIN - 1)    // 42 walk rows staged per block
#define STAGE_V  (ROWS_PER * NVEC)        // 1344 float4 copies per block

__device__ __forceinline__ float warp_reduce_sum(float v) {
    v += __shfl_xor_sync(0xffffffffu, v, 16);
    v += __shfl_xor_sync(0xffffffffu, v, 8);
    v += __shfl_xor_sync(0xffffffffu, v, 4);
    v += __shfl_xor_sync(0xffffffffu, v, 2);
    v += __shfl_xor_sync(0xffffffffu, v, 1);
    return v;
}

// Pairwise combining reduce: lanes with (lane & off)==0 end up holding the
// a-reduction, lanes with the bit set hold the b-reduction.
__device__ __forceinline__ float cmb(float a, float b, int off, int lane) {
    float send = (lane & off) ? a : b;
    float keep = (lane & off) ? b : a;
    return keep + __shfl_xor_sync(0xffffffffu, send, off);
}

// softplus(x) = max(x,0) + log(1 + exp(-|x|)); fast-math variants are
// accurate to ~1e-7 absolute here, far inside the 1e-3 rel-err budget.
__device__ __forceinline__ float softplus_f(float x) {
    return fmaxf(x, 0.0f) + __logf(1.0f + __expf(-fabsf(x)));
}

__device__ __forceinline__ float dot4(float4 a, float4 b) {
    return a.x * b.x + a.y * b.y + a.z * b.z + a.w * b.w;
}

// The 8-dot tail shared by the peeled iteration and the main loop:
// multi-value warp reduction (9 shfls) + parallel softplus on 8 lanes.
__device__ __forceinline__ float reduce8_softplus(
    float p0, float p1, float p2, float p3,
    float p4, float p5, float p6, float p7, int lane) {
    float r10 = cmb(p0, p4, 16, lane);
    float r11 = cmb(p1, p5, 16, lane);
    float r12 = cmb(p2, p6, 16, lane);
    float r13 = cmb(p3, p7, 16, lane);
    float q0  = cmb(r10, r11, 8, lane);
    float q1  = cmb(r12, r13, 8, lane);
    float r   = cmb(q0, q1, 4, lane);
    r += __shfl_xor_sync(0xffffffffu, r, 2);
    r += __shfl_xor_sync(0xffffffffu, r, 1);
    // Lanes 0,4,...,28 hold the 8 dots; bit16 => neg logit (softplus(+x)).
    if ((lane & 3) == 0) {
        const float x = (lane & 16) ? r : -r;
        return softplus_f(x);
    }
    return 0.0f;
}

__global__ __launch_bounds__(NTHREADS, 8)
void sgns_kernel(const int* __restrict__ walk,
                 const int* __restrict__ neg,
                 const float* __restrict__ embed,
                 float* __restrict__ out,
                 float inv_total) {
    __shared__ float4 srow[ROWS_PER][NVEC];   // 42 x 512B = 21.5 KB
    __shared__ int    swalk[ROWS_PER];
    __shared__ int    sneg[ANC_PER * NNEG];   // 152 ints
    __shared__ float  wsum[NWARPS];

    const int bid  = blockIdx.x;
    const int wb   = bid >> 1;                // walk index
    const int base = (bid & 1) * ANC_PER;     // first anchor of this half
    const int tid  = threadIdx.x;
    const int lane = tid & 31;
    const int wid  = tid >> 5;

    if (tid < ROWS_PER)
        swalk[tid] = walk[(size_t)wb * L_WALK + base + tid];
    if (tid < ANC_PER * NNEG)
        sneg[tid] = neg[((size_t)wb * A_ANC + base) * NNEG + tid];
    __syncthreads();

    // Stage the 42 walk-row embeddings (1344 float4s, flat-indexed) with
    // batched independent LDGs (MLP=3 per batch) -- the proven prologue.
    {
        const int f0 = tid, f1 = tid + NTHREADS, f2 = tid + 2 * NTHREADS;
        const float4 t0 = __ldg((const float4*)(embed + (size_t)swalk[f0 >> 5] * DIM) + (f0 & 31));
        const float4 t1 = __ldg((const float4*)(embed + (size_t)swalk[f1 >> 5] * DIM) + (f1 & 31));
        const float4 t2 = __ldg((const float4*)(embed + (size_t)swalk[f2 >> 5] * DIM) + (f2 & 31));
        srow[f0 >> 5][f0 & 31] = t0;
        srow[f1 >> 5][f1 & 31] = t1;
        srow[f2 >> 5][f2 & 31] = t2;
    }
    {
        const int f3 = tid + 3 * NTHREADS, f4 = tid + 4 * NTHREADS, f5 = tid + 5 * NTHREADS;
        const float4 t3 = __ldg((const float4*)(embed + (size_t)swalk[f3 >> 5] * DIM) + (f3 & 31));
        const float4 t4 = __ldg((const float4*)(embed + (size_t)swalk[f4 >> 5] * DIM) + (f4 & 31));
        float4 t5;
        const bool ok5 = (f5 < STAGE_V);
        if (ok5) t5 = __ldg((const float4*)(embed + (size_t)swalk[f5 >> 5] * DIM) + (f5 & 31));
        srow[f3 >> 5][f3 & 31] = t3;
        srow[f4 >> 5][f4 & 31] = t4;
        if (ok5) srow[f5 >> 5][f5 & 31] = t5;
    }

    float acc = 0.0f;   // per-lane partial (8 softplus lanes contribute)

    // Peel iteration 0: issue this warp's first-anchor gathers BEFORE the
    // staging barrier so their DRAM latency rides out the barrier wait.
    // (sneg is valid -- written before the first __syncthreads.)
    {
        const int a0 = wid;   // NWARPS(8) <= ANC_PER(38), always valid
        const float4 v0 = __ldg((const float4*)(embed + (size_t)sneg[a0 * NNEG + 0] * DIM) + lane);
        const float4 v1 = __ldg((const float4*)(embed + (size_t)sneg[a0 * NNEG + 1] * DIM) + lane);
        const float4 v2 = __ldg((const float4*)(embed + (size_t)sneg[a0 * NNEG + 2] * DIM) + lane);
        const float4 v3 = __ldg((const float4*)(embed + (size_t)sneg[a0 * NNEG + 3] * DIM) + lane);

        __syncthreads();   // staging complete; gathers still in flight

        const float4 va = srow[a0][lane];
        const float p0 = dot4(va, srow[a0 + 1][lane]);
        const float p1 = dot4(va, srow[a0 + 2][lane]);
        const float p2 = dot4(va, srow[a0 + 3][lane]);
        const float p3 = dot4(va, srow[a0 + 4][lane]);
        const float p4 = dot4(va, v0);
        const float p5 = dot4(va, v1);
        const float p6 = dot4(va, v2);
        const float p7 = dot4(va, v3);
        acc += reduce8_softplus(p0, p1, p2, p3, p4, p5, p6, p7, lane);
    }

    // Remaining anchors: R9 main loop verbatim (issue-early gathers).
    for (int a = wid + NWARPS; a < ANC_PER; a += NWARPS) {
        const int i0 = sneg[a * NNEG + 0];
        const int i1 = sneg[a * NNEG + 1];
        const int i2 = sneg[a * NNEG + 2];
        const int i3 = sneg[a * NNEG + 3];
        const float4 v0 = __ldg((const float4*)(embed + (size_t)i0 * DIM) + lane);
        const float4 v1 = __ldg((const float4*)(embed + (size_t)i1 * DIM) + lane);
        const float4 v2 = __ldg((const float4*)(embed + (size_t)i2 * DIM) + lane);
        const float4 v3 = __ldg((const float4*)(embed + (size_t)i3 * DIM) + lane);

        const float4 va = srow[a][lane];

        const float p0 = dot4(va, srow[a + 1][lane]);
        const float p1 = dot4(va, srow[a + 2][lane]);
        const float p2 = dot4(va, srow[a + 3][lane]);
        const float p3 = dot4(va, srow[a + 4][lane]);

        const float p4 = dot4(va, v0);
        const float p5 = dot4(va, v1);
        const float p6 = dot4(va, v2);
        const float p7 = dot4(va, v3);

        acc += reduce8_softplus(p0, p1, p2, p3, p4, p5, p6, p7, lane);
    }

    acc = warp_reduce_sum(acc);
    if (lane == 0) wsum[wid] = acc;
    __syncthreads();

    if (tid == 0) {
        float s = 0.0f;
        #pragma unroll
        for (int i = 0; i < NWARPS; i++) s += wsum[i];
        atomicAdd(out, s * inv_total);
    }
}

extern "C" void kernel_launch(void* const* d_in, const int* in_sizes, int n_in,
                              void* d_out, int out_size) {
    const int*   walk  = (const int*)d_in[0];
    const int*   neg   = (const int*)d_in[1];
    const float* embed = (const float*)d_in[2];
    float*       out   = (float*)d_out;

    const int B = in_sizes[0] / L_WALK;                 // 1024
    const float inv_total = 1.0f / ((float)B * A_ANC * (W_WIN - 1 + NNEG));

    // Zero the scalar accumulator with a memset node (cheaper than a kernel).
    cudaMemsetAsync(out, 0, sizeof(float));
    sgns_kernel<<<B * SPLIT, NTHREADS>>>(walk, neg, embed, out, inv_total);
}